// round 9
// baseline (speedup 1.0000x reference)
#include <cuda_runtime.h>
#include <cstdint>

#define N_ROWS 6400
#define DIMV 64
#define NUM_EMB 512
#define GROUP 100
#define NSPLIT 8
#define TILES_PER_SPLIT 13   // 7*13 + 9 = 100 key tiles of 64

// ---- scratch (no cudaMalloc allowed); +1024 pad so 64-row tile reads
// starting at row 6350 never go OOB ----
__device__ float g_qis[N_ROWS * DIMV + 1024];
__device__ float g_kis[N_ROWS * DIMV + 1024];
__device__ float g_vis[N_ROWS * DIMV + 1024];
__device__ float g_qcs[N_ROWS * DIMV + 1024];
__device__ float g_kcs[N_ROWS * DIMV + 1024];
__device__ float g_vcs[N_ROWS * DIMV + 1024];
__device__ float g_Opart[NSPLIT][N_ROWS * DIMV];
__device__ float g_mpart[NSPLIT][N_ROWS];
__device__ float g_lpart[NSPLIT][N_ROWS];

__device__ __forceinline__ uint32_t f2tf(float f) {
    uint32_t u;
    asm("cvt.rna.tf32.f32 %0, %1;" : "=r"(u) : "f"(f));
    return u;
}

__device__ __forceinline__ void mma_tf32(
    float* d,
    uint32_t a0, uint32_t a1, uint32_t a2, uint32_t a3,
    uint32_t b0, uint32_t b1)
{
    asm volatile(
        "mma.sync.aligned.m16n8k8.row.col.f32.tf32.tf32.f32 "
        "{%0,%1,%2,%3},{%4,%5,%6,%7},{%8,%9},{%0,%1,%2,%3};\n"
        : "+f"(d[0]), "+f"(d[1]), "+f"(d[2]), "+f"(d[3])
        : "r"(a0), "r"(a1), "r"(a2), "r"(a3), "r"(b0), "r"(b1));
}

// ============================================================
// Kernel 1: fused quantization + projections, 128 threads, 65KB dyn smem.
//   bid 0..99   : vector quantization (3-term tf32 MMA + argmin), 64 rows
//   bid 100..699: projection p=(bid-100)/100, 64-row block, 3-term tf32 MMA
// ============================================================
__global__ __launch_bounds__(128) void quant_proj_kernel(
    const float* __restrict__ x, const float* __restrict__ cb,
    float* __restrict__ out,
    const float* __restrict__ W0, const float* __restrict__ b0,
    const float* __restrict__ W1, const float* __restrict__ b1,
    const float* __restrict__ W2, const float* __restrict__ b2,
    const float* __restrict__ W3, const float* __restrict__ b3,
    const float* __restrict__ W4, const float* __restrict__ b4,
    const float* __restrict__ W5, const float* __restrict__ b5)
{
    extern __shared__ uint32_t smbuf[];
    int t = threadIdx.x;
    int wm = t >> 5, lane = t & 31;
    int g = lane >> 2, c4 = lane & 3;
    int rL = (wm * 16 + g) * 64;

    if (blockIdx.x >= 100) {
        // ================= projection (tf32 MMA, 3-term) =================
        uint32_t* Fh = smbuf;             // 4096
        uint32_t* Fl = smbuf + 4096;      // 4096
        uint32_t* Wh = smbuf + 8192;      // 4096 (W^T, n-major k-swizzled)
        uint32_t* Wl = smbuf + 12288;     // 4096
        float* bsm = (float*)(smbuf + 16384);  // 64

        int bid = blockIdx.x - 100;
        int p = bid / 100;
        int rowBase = (bid % 100) * 64;

        const float* Wlst[6] = {W0, W1, W2, W3, W4, W5};
        const float* blst[6] = {b0, b1, b2, b3, b4, b5};
        float* olst[6] = {g_qis, g_kis, g_vis, g_qcs, g_kcs, g_vcs};
        const float* W = Wlst[p];
        float* o = olst[p];

        // x rows -> A layout (row-major, row&7 swizzle), hi/lo split
        const float4* Xg = (const float4*)(x + rowBase * 64);
        for (int i = t; i < 1024; i += 128) {
            int row = i >> 4, j = i & 15;
            float4 f = Xg[i];
            uint32_t h0 = f2tf(f.x), h1 = f2tf(f.y), h2 = f2tf(f.z), h3 = f2tf(f.w);
            int ad = row * 64 + 4 * (j ^ (row & 7));
            *(uint4*)(Fh + ad) = make_uint4(h0, h1, h2, h3);
            *(uint4*)(Fl + ad) = make_uint4(
                f2tf(f.x - __uint_as_float(h0)), f2tf(f.y - __uint_as_float(h1)),
                f2tf(f.z - __uint_as_float(h2)), f2tf(f.w - __uint_as_float(h3)));
        }
        // W -> B layout (transpose in smem): word (n, k) at n*64 + 4*((k>>2)^(n&7)) + (k&3)
        const float4* Wg4 = (const float4*)W;
        for (int i = t; i < 1024; i += 128) {
            int d = 4 * (i >> 6) + (i & 3);   // k index
            int c = (i >> 2) & 15;            // float4 column group
            float4 f = Wg4[d * 16 + c];
            int kp = 4 * (d >> 2) ;           // base of swizzle input
            float v[4] = {f.x, f.y, f.z, f.w};
#pragma unroll
            for (int e = 0; e < 4; e++) {
                int n = 4 * c + e;
                int ad = n * 64 + 4 * ((kp >> 2) ^ (n & 7)) + (d & 3);
                uint32_t h = f2tf(v[e]);
                Wh[ad] = h;
                Wl[ad] = f2tf(v[e] - __uint_as_float(h));
            }
        }
        if (t < 64) bsm[t] = blst[p][t];
        __syncthreads();

        float S[8][4];
#pragma unroll
        for (int n = 0; n < 8; n++)
#pragma unroll
            for (int j = 0; j < 4; j++) S[n][j] = 0.f;

#pragma unroll
        for (int k0 = 0; k0 < 8; k0++) {
            int ch0 = 4 * ((2 * k0) ^ g);
            int ch1 = 4 * ((2 * k0 + 1) ^ g);
            uint32_t ah0 = Fh[rL + ch0 + c4], ah1 = Fh[rL + 512 + ch0 + c4];
            uint32_t ah2 = Fh[rL + ch1 + c4], ah3 = Fh[rL + 512 + ch1 + c4];
            uint32_t al0 = Fl[rL + ch0 + c4], al1 = Fl[rL + 512 + ch0 + c4];
            uint32_t al2 = Fl[rL + ch1 + c4], al3 = Fl[rL + 512 + ch1 + c4];
#pragma unroll
            for (int n0 = 0; n0 < 8; n0++) {
                int key = n0 * 8 + g;
                uint32_t bh0 = Wh[key * 64 + ch0 + c4];
                uint32_t bh1 = Wh[key * 64 + ch1 + c4];
                uint32_t bl0 = Wl[key * 64 + ch0 + c4];
                uint32_t bl1 = Wl[key * 64 + ch1 + c4];
                mma_tf32(S[n0], ah0, ah1, ah2, ah3, bh0, bh1);
                mma_tf32(S[n0], ah0, ah1, ah2, ah3, bl0, bl1);
                mma_tf32(S[n0], al0, al1, al2, al3, bh0, bh1);
            }
        }

        int rA = rowBase + wm * 16 + g;
#pragma unroll
        for (int n0 = 0; n0 < 8; n0++) {
            int col = n0 * 8 + 2 * c4;
            float bb0 = bsm[col], bb1 = bsm[col + 1];
            *(float2*)(o + rA * 64 + col) = make_float2(
                __uint_as_float(f2tf(S[n0][0] + bb0)),
                __uint_as_float(f2tf(S[n0][1] + bb1)));
            *(float2*)(o + (rA + 8) * 64 + col) = make_float2(
                __uint_as_float(f2tf(S[n0][2] + bb0)),
                __uint_as_float(f2tf(S[n0][3] + bb1)));
        }
        return;
    }

    // ================= quantization =================
    uint32_t* Fh = smbuf;            // 4096
    uint32_t* Fl = smbuf + 4096;     // 4096
    uint32_t* Ch = smbuf + 8192;     // 4096
    uint32_t* Cl = smbuf + 12288;    // 4096
    float* cns = (float*)(smbuf + 16384);  // 64

    int rBase = blockIdx.x * 64;
    const float4* Fg = (const float4*)(x + rBase * 64);
    for (int i = t; i < 1024; i += 128) {
        int row = i >> 4, j = i & 15;
        float4 f = Fg[i];
        uint32_t h0 = f2tf(f.x), h1 = f2tf(f.y), h2 = f2tf(f.z), h3 = f2tf(f.w);
        int ad = row * 64 + 4 * (j ^ (row & 7));
        *(uint4*)(Fh + ad) = make_uint4(h0, h1, h2, h3);
        *(uint4*)(Fl + ad) = make_uint4(
            f2tf(f.x - __uint_as_float(h0)), f2tf(f.y - __uint_as_float(h1)),
            f2tf(f.z - __uint_as_float(h2)), f2tf(f.w - __uint_as_float(h3)));
    }

    float bA = 3.4e38f, bB = 3.4e38f;
    int iA = 0, iB = 0;

    for (int ct = 0; ct < 8; ct++) {
        __syncthreads();
        const float4* Cg = (const float4*)(cb + ct * 64 * 64);
        for (int i = t; i < 1024; i += 128) {
            int code = i >> 4, j = i & 15;
            float4 f = Cg[i];
            uint32_t h0 = f2tf(f.x), h1 = f2tf(f.y), h2 = f2tf(f.z), h3 = f2tf(f.w);
            int ad = code * 64 + 4 * (j ^ (code & 7));
            *(uint4*)(Ch + ad) = make_uint4(h0, h1, h2, h3);
            *(uint4*)(Cl + ad) = make_uint4(
                f2tf(f.x - __uint_as_float(h0)), f2tf(f.y - __uint_as_float(h1)),
                f2tf(f.z - __uint_as_float(h2)), f2tf(f.w - __uint_as_float(h3)));
        }
        __syncthreads();
        if (t < 64) {
            float s = 0.f;
#pragma unroll
            for (int j = 0; j < 16; j++) {
                int ad = t * 64 + 4 * (j ^ (t & 7));
                uint4 h = *(uint4*)(Ch + ad);
                uint4 l = *(uint4*)(Cl + ad);
                float v;
                v = __uint_as_float(h.x) + __uint_as_float(l.x); s = fmaf(v, v, s);
                v = __uint_as_float(h.y) + __uint_as_float(l.y); s = fmaf(v, v, s);
                v = __uint_as_float(h.z) + __uint_as_float(l.z); s = fmaf(v, v, s);
                v = __uint_as_float(h.w) + __uint_as_float(l.w); s = fmaf(v, v, s);
            }
            cns[t] = s;
        }
        __syncthreads();

        float S[8][4];
#pragma unroll
        for (int n = 0; n < 8; n++)
#pragma unroll
            for (int j = 0; j < 4; j++) S[n][j] = 0.f;

#pragma unroll
        for (int k0 = 0; k0 < 8; k0++) {
            int ch0 = 4 * ((2 * k0) ^ g);
            int ch1 = 4 * ((2 * k0 + 1) ^ g);
            uint32_t ah0 = Fh[rL + ch0 + c4], ah1 = Fh[rL + 512 + ch0 + c4];
            uint32_t ah2 = Fh[rL + ch1 + c4], ah3 = Fh[rL + 512 + ch1 + c4];
            uint32_t al0 = Fl[rL + ch0 + c4], al1 = Fl[rL + 512 + ch0 + c4];
            uint32_t al2 = Fl[rL + ch1 + c4], al3 = Fl[rL + 512 + ch1 + c4];
#pragma unroll
            for (int n0 = 0; n0 < 8; n0++) {
                int key = n0 * 8 + g;
                uint32_t bh0 = Ch[key * 64 + ch0 + c4];
                uint32_t bh1 = Ch[key * 64 + ch1 + c4];
                uint32_t bl0 = Cl[key * 64 + ch0 + c4];
                uint32_t bl1 = Cl[key * 64 + ch1 + c4];
                mma_tf32(S[n0], ah0, ah1, ah2, ah3, bh0, bh1);
                mma_tf32(S[n0], ah0, ah1, ah2, ah3, bl0, bl1);
                mma_tf32(S[n0], al0, al1, al2, al3, bh0, bh1);
            }
        }

#pragma unroll
        for (int n0 = 0; n0 < 8; n0++) {
            int c0 = n0 * 8 + 2 * c4;
            float cn0 = cns[c0], cn1 = cns[c0 + 1];
            int gi = ct * 64 + c0;
            float d;
            d = cn0 - 2.f * S[n0][0];
            if (d < bA || (d == bA && gi < iA)) { bA = d; iA = gi; }
            d = cn1 - 2.f * S[n0][1];
            if (d < bA || (d == bA && gi + 1 < iA)) { bA = d; iA = gi + 1; }
            d = cn0 - 2.f * S[n0][2];
            if (d < bB || (d == bB && gi < iB)) { bB = d; iB = gi; }
            d = cn1 - 2.f * S[n0][3];
            if (d < bB || (d == bB && gi + 1 < iB)) { bB = d; iB = gi + 1; }
        }
    }
#pragma unroll
    for (int off = 1; off <= 2; off <<= 1) {
        float ob; int oi;
        ob = __shfl_xor_sync(0xffffffffu, bA, off);
        oi = __shfl_xor_sync(0xffffffffu, iA, off);
        if (ob < bA || (ob == bA && oi < iA)) { bA = ob; iA = oi; }
        ob = __shfl_xor_sync(0xffffffffu, bB, off);
        oi = __shfl_xor_sync(0xffffffffu, iB, off);
        if (ob < bB || (ob == bB && oi < iB)) { bB = ob; iB = oi; }
    }
    int rA = rBase + wm * 16 + g;
    const float4* cbA = (const float4*)(cb + iA * 64);
    const float4* cbB = (const float4*)(cb + iB * 64);
    float4* oA = (float4*)(out + rA * 64);
    float4* oB = (float4*)(out + (rA + 8) * 64);
#pragma unroll
    for (int j = 0; j < 4; j++) {
        oA[c4 * 4 + j] = cbA[c4 * 4 + j];
        oB[c4 * 4 + j] = cbB[c4 * 4 + j];
    }
}

// ============================================================
// Kernel 2: fused attention. 128 threads, 96KB dyn smem.
//   bid 0..399   : CS flash split-K (tf32 MMA), NSPLIT=8
//   bid 400..527 : IS attention (tf32 MMA, single 64-pad tile)
// ============================================================
__global__ __launch_bounds__(128) void attn_kernel(float* __restrict__ out)
{
    extern __shared__ uint32_t smbuf[];
    int t = threadIdx.x;
    int wm = t >> 5, lane = t & 31;
    int g = lane >> 2, c4 = lane & 3;

    float* outZ = out + N_ROWS * DIMV;

    if (blockIdx.x >= 400) {
        // ================= IS attention =================
        uint32_t* Qs = smbuf;
        uint32_t* Ks = smbuf + 4096;
        uint32_t* Vs = smbuf + 8192;
        uint32_t* Ps = smbuf + 12288;
        int base = (blockIdx.x - 400) * 50;

        const uint4* Qg = (const uint4*)(g_kis + base * 64);
        const uint4* Kg = (const uint4*)(g_qis + base * 64);
        const uint4* Vg = (const uint4*)(g_vis + base * 64);
        for (int i = t; i < 1024; i += 128) {
            int row = i >> 4, j = i & 15;
            *(uint4*)(Qs + row * 64 + 4 * (j ^ (row & 7)))       = Qg[i];
            *(uint4*)(Ks + row * 64 + 4 * (j ^ (row & 7)))       = Kg[i];
            *(uint4*)(Vs + row * 64 + 4 * (j ^ (2 * (row & 3)))) = Vg[i];
        }
        __syncthreads();

        int rL = (wm * 16 + g) * 64;
        float S[8][4];
#pragma unroll
        for (int n = 0; n < 8; n++)
#pragma unroll
            for (int j = 0; j < 4; j++) S[n][j] = 0.f;

#pragma unroll
        for (int k0 = 0; k0 < 8; k0++) {
            int ch0 = 4 * ((2 * k0) ^ g);
            int ch1 = 4 * ((2 * k0 + 1) ^ g);
            uint32_t a0 = Qs[rL + ch0 + c4];
            uint32_t a1 = Qs[rL + 512 + ch0 + c4];
            uint32_t a2 = Qs[rL + ch1 + c4];
            uint32_t a3 = Qs[rL + 512 + ch1 + c4];
#pragma unroll
            for (int n0 = 0; n0 < 8; n0++) {
                int key = n0 * 8 + g;
                uint32_t b0 = Ks[key * 64 + ch0 + c4];
                uint32_t b1 = Ks[key * 64 + ch1 + c4];
                mma_tf32(S[n0], a0, a1, a2, a3, b0, b1);
            }
        }

        float rmA = -1e30f, rmB = -1e30f;
#pragma unroll
        for (int n0 = 0; n0 < 8; n0++) {
            int col0 = n0 * 8 + 2 * c4;
            if (col0 >= 50)     { S[n0][0] = -1e30f; S[n0][2] = -1e30f; }
            if (col0 + 1 >= 50) { S[n0][1] = -1e30f; S[n0][3] = -1e30f; }
            rmA = fmaxf(rmA, fmaxf(S[n0][0], S[n0][1]));
            rmB = fmaxf(rmB, fmaxf(S[n0][2], S[n0][3]));
        }
        rmA = fmaxf(rmA, __shfl_xor_sync(0xffffffffu, rmA, 1));
        rmA = fmaxf(rmA, __shfl_xor_sync(0xffffffffu, rmA, 2));
        rmB = fmaxf(rmB, __shfl_xor_sync(0xffffffffu, rmB, 1));
        rmB = fmaxf(rmB, __shfl_xor_sync(0xffffffffu, rmB, 2));

        float lsA = 0.f, lsB = 0.f;
#pragma unroll
        for (int n0 = 0; n0 < 8; n0++) {
            float pA0 = __expf(S[n0][0] - rmA);
            float pA1 = __expf(S[n0][1] - rmA);
            float pB0 = __expf(S[n0][2] - rmB);
            float pB1 = __expf(S[n0][3] - rmB);
            lsA += pA0 + pA1;
            lsB += pB0 + pB1;
            int chp = 4 * ((2 * n0 + (c4 >> 1)) ^ g) + ((2 * c4) & 3);
            *(uint2*)(Ps + rL + chp)       = make_uint2(f2tf(pA0), f2tf(pA1));
            *(uint2*)(Ps + rL + 512 + chp) = make_uint2(f2tf(pB0), f2tf(pB1));
        }
        lsA += __shfl_xor_sync(0xffffffffu, lsA, 1);
        lsA += __shfl_xor_sync(0xffffffffu, lsA, 2);
        lsB += __shfl_xor_sync(0xffffffffu, lsB, 1);
        lsB += __shfl_xor_sync(0xffffffffu, lsB, 2);
        __syncwarp();

        float O[8][4];
#pragma unroll
        for (int n = 0; n < 8; n++)
#pragma unroll
            for (int j = 0; j < 4; j++) O[n][j] = 0.f;

#pragma unroll
        for (int k0 = 0; k0 < 8; k0++) {
            int ch0 = 4 * ((2 * k0) ^ g);
            int ch1 = 4 * ((2 * k0 + 1) ^ g);
            uint32_t a0 = Ps[rL + ch0 + c4];
            uint32_t a1 = Ps[rL + 512 + ch0 + c4];
            uint32_t a2 = Ps[rL + ch1 + c4];
            uint32_t a3 = Ps[rL + 512 + ch1 + c4];
            int ky0 = (k0 * 8 + c4) * 64;
            int ky1 = ky0 + 256;
            int sw = 2 * c4;
#pragma unroll
            for (int n0 = 0; n0 < 8; n0++) {
                int ch = 4 * ((2 * n0 + (g >> 2)) ^ sw) + (g & 3);
                uint32_t b0 = Vs[ky0 + ch];
                uint32_t b1 = Vs[ky1 + ch];
                mma_tf32(O[n0], a0, a1, a2, a3, b0, b1);
            }
        }

        float invA = 1.f / lsA, invB = 1.f / lsB;
        int r0 = wm * 16 + g;
#pragma unroll
        for (int n0 = 0; n0 < 8; n0++) {
            int col = n0 * 8 + 2 * c4;
            if (r0 < 50)
                *(float2*)(outZ + (base + r0) * 64 + col) =
                    make_float2(O[n0][0] * invA, O[n0][1] * invA);
            if (r0 + 8 < 50)
                *(float2*)(outZ + (base + r0 + 8) * 64 + col) =
                    make_float2(O[n0][2] * invB, O[n0][3] * invB);
        }
        return;
    }

    // ================= CS attention (flash + split-K) =================
    uint32_t* Qs = smbuf;            // 8192 words
    uint32_t* Ks = smbuf + 8192;     // 4096
    uint32_t* Vs = smbuf + 12288;    // 4096
    uint32_t* Ps = smbuf + 16384;    // 8192

    int bid = blockIdx.x;
    int qt = bid / NSPLIT, sp = bid % NSPLIT;
    int qBase = qt * 128;

    {
        const uint4* Qg = (const uint4*)(g_kcs + qBase * 64);
        for (int i = t; i < 2048; i += 128) {
            int row = i >> 4, j = i & 15;
            *(uint4*)(Qs + row * 64 + 4 * (j ^ (row & 7))) = Qg[i];
        }
    }

    float S[2][8][4];
    float O[2][8][4];
#pragma unroll
    for (int b = 0; b < 2; b++)
#pragma unroll
        for (int n = 0; n < 8; n++)
#pragma unroll
            for (int j = 0; j < 4; j++) O[b][n][j] = 0.f;

    float mv[4], lv[4];
    int qsamp[4];
#pragma unroll
    for (int s = 0; s < 4; s++) {
        mv[s] = -1e30f; lv[s] = 0.f;
        int row = qBase + wm * 32 + (s >> 1) * 16 + (s & 1) * 8 + g;
        qsamp[s] = row / GROUP;
    }

    int ktStart = sp * TILES_PER_SPLIT;
    int ktEnd = ktStart + TILES_PER_SPLIT;
    if (ktEnd > 100) ktEnd = 100;

    for (int kt = ktStart; kt < ktEnd; kt++) {
        __syncthreads();
        int kBase = kt * 64;
        {
            const uint4* Kg = (const uint4*)(g_qcs + kBase * 64);
            const uint4* Vg = (const uint4*)(g_vcs + kBase * 64);
            for (int i = t; i < 1024; i += 128) {
                int key = i >> 4, j = i & 15;
                *(uint4*)(Ks + key * 64 + 4 * (j ^ (key & 7)))       = Kg[i];
                *(uint4*)(Vs + key * 64 + 4 * (j ^ (2 * (key & 3)))) = Vg[i];
            }
        }
        __syncthreads();

#pragma unroll
        for (int b = 0; b < 2; b++)
#pragma unroll
            for (int n = 0; n < 8; n++)
#pragma unroll
                for (int j = 0; j < 4; j++) S[b][n][j] = 0.f;

#pragma unroll
        for (int k0 = 0; k0 < 8; k0++) {
            int ch0 = 4 * ((2 * k0) ^ g);
            int ch1 = 4 * ((2 * k0 + 1) ^ g);
            uint32_t a[2][4];
#pragma unroll
            for (int b = 0; b < 2; b++) {
                int rL = (wm * 32 + b * 16 + g) * 64;
                a[b][0] = Qs[rL + ch0 + c4];
                a[b][1] = Qs[rL + 512 + ch0 + c4];
                a[b][2] = Qs[rL + ch1 + c4];
                a[b][3] = Qs[rL + 512 + ch1 + c4];
            }
#pragma unroll
            for (int n0 = 0; n0 < 8; n0++) {
                int key = n0 * 8 + g;
                uint32_t b0 = Ks[key * 64 + ch0 + c4];
                uint32_t b1 = Ks[key * 64 + ch1 + c4];
                mma_tf32(S[0][n0], a[0][0], a[0][1], a[0][2], a[0][3], b0, b1);
                mma_tf32(S[1][n0], a[1][0], a[1][1], a[1][2], a[1][3], b0, b1);
            }
        }

        float rm[4] = {-1e30f, -1e30f, -1e30f, -1e30f};
#pragma unroll
        for (int n0 = 0; n0 < 8; n0++) {
            int col0 = kBase + n0 * 8 + 2 * c4;
            int cs0 = col0 / GROUP, cs1 = (col0 + 1) / GROUP;
#pragma unroll
            for (int s = 0; s < 4; s++) {
                int b = s >> 1, h = s & 1;
                if (cs0 == qsamp[s]) S[b][n0][2 * h]     = -1e30f;
                if (cs1 == qsamp[s]) S[b][n0][2 * h + 1] = -1e30f;
                rm[s] = fmaxf(rm[s], fmaxf(S[b][n0][2 * h], S[b][n0][2 * h + 1]));
            }
        }
        float corr[4];
#pragma unroll
        for (int s = 0; s < 4; s++) {
            rm[s] = fmaxf(rm[s], __shfl_xor_sync(0xffffffffu, rm[s], 1));
            rm[s] = fmaxf(rm[s], __shfl_xor_sync(0xffffffffu, rm[s], 2));
            float mn = fmaxf(mv[s], rm[s]);
            corr[s] = __expf(mv[s] - mn);
            mv[s] = mn;
        }
        float ls[4] = {0.f, 0.f, 0.f, 0.f};
#pragma unroll
        for (int n0 = 0; n0 < 8; n0++) {
            int chp = 4 * ((2 * n0 + (c4 >> 1)) ^ g) + ((2 * c4) & 3);
#pragma unroll
            for (int s = 0; s < 4; s++) {
                int b = s >> 1, h = s & 1;
                float p0 = __expf(S[b][n0][2 * h]     - mv[s]);
                float p1 = __expf(S[b][n0][2 * h + 1] - mv[s]);
                ls[s] += p0 + p1;
                int row = wm * 32 + b * 16 + h * 8 + g;
                *(uint2*)(Ps + row * 64 + chp) = make_uint2(f2tf(p0), f2tf(p1));
            }
        }
#pragma unroll
        for (int s = 0; s < 4; s++) {
            ls[s] += __shfl_xor_sync(0xffffffffu, ls[s], 1);
            ls[s] += __shfl_xor_sync(0xffffffffu, ls[s], 2);
            lv[s] = lv[s] * corr[s] + ls[s];
            int b = s >> 1, h = s & 1;
#pragma unroll
            for (int n0 = 0; n0 < 8; n0++) {
                O[b][n0][2 * h]     *= corr[s];
                O[b][n0][2 * h + 1] *= corr[s];
            }
        }
        __syncwarp();

#pragma unroll
        for (int k0 = 0; k0 < 8; k0++) {
            int ch0 = 4 * ((2 * k0) ^ g);
            int ch1 = 4 * ((2 * k0 + 1) ^ g);
            uint32_t a[2][4];
#pragma unroll
            for (int b = 0; b < 2; b++) {
                int rL = (wm * 32 + b * 16 + g) * 64;
                a[b][0] = Ps[rL + ch0 + c4];
                a[b][1] = Ps[rL + 512 + ch0 + c4];
                a[b][2] = Ps[rL + ch1 + c4];
                a[b][3] = Ps[rL + 512 + ch1 + c4];
            }
            int ky0 = (k0 * 8 + c4) * 64;
            int ky1 = ky0 + 256;
            int sw = 2 * c4;
#pragma unroll
            for (int n0 = 0; n0 < 8; n0++) {
                int ch = 4 * ((2 * n0 + (g >> 2)) ^ sw) + (g & 3);
                uint32_t b0 = Vs[ky0 + ch];
                uint32_t b1 = Vs[ky1 + ch];
                mma_tf32(O[0][n0], a[0][0], a[0][1], a[0][2], a[0][3], b0, b1);
                mma_tf32(O[1][n0], a[1][0], a[1][1], a[1][2], a[1][3], b0, b1);
            }
        }
    }

    float* Op = g_Opart[sp];
#pragma unroll
    for (int b = 0; b < 2; b++) {
        int rowA = qBase + wm * 32 + b * 16 + g;
#pragma unroll
        for (int n0 = 0; n0 < 8; n0++) {
            int col = n0 * 8 + 2 * c4;
            *(float2*)(Op + rowA * 64 + col)       = make_float2(O[b][n0][0], O[b][n0][1]);
            *(float2*)(Op + (rowA + 8) * 64 + col) = make_float2(O[b][n0][2], O[b][n0][3]);
        }
    }
    if (c4 == 0) {
#pragma unroll
        for (int s = 0; s < 4; s++) {
            int row = qBase + wm * 32 + (s >> 1) * 16 + (s & 1) * 8 + g;
            g_mpart[sp][row] = mv[s];
            g_lpart[sp][row] = lv[s];
        }
    }
}

// ============================================================
// Kernel 3: combine split-K partials.
// ============================================================
__global__ __launch_bounds__(256) void cs_combine_kernel(float* __restrict__ outX)
{
    int gidx = blockIdx.x * 256 + threadIdx.x;
    int row = gidx >> 4;
    int e4 = gidx & 15;
    if (row >= N_ROWS) return;

    float m[NSPLIT];
    float M = -3.4e38f;
#pragma unroll
    for (int s = 0; s < NSPLIT; s++) { m[s] = g_mpart[s][row]; M = fmaxf(M, m[s]); }
    float wgt[NSPLIT];
    float denom = 0.f;
#pragma unroll
    for (int s = 0; s < NSPLIT; s++) {
        wgt[s] = __expf(m[s] - M);
        denom += wgt[s] * g_lpart[s][row];
    }
    float inv = 1.f / denom;

    float4 o = {0.f, 0.f, 0.f, 0.f};
#pragma unroll
    for (int s = 0; s < NSPLIT; s++) {
        float4 a = ((const float4*)g_Opart[s])[row * 16 + e4];
        o.x = fmaf(a.x, wgt[s], o.x);
        o.y = fmaf(a.y, wgt[s], o.y);
        o.z = fmaf(a.z, wgt[s], o.z);
        o.w = fmaf(a.w, wgt[s], o.w);
    }
    o.x *= inv; o.y *= inv; o.z *= inv; o.w *= inv;
    ((float4*)outX)[row * 16 + e4] = o;
}

// ============================================================
extern "C" void kernel_launch(void* const* d_in, const int* in_sizes, int n_in,
                              void* d_out, int out_size)
{
    const float* x    = (const float*)d_in[0];
    const float* cb   = (const float*)d_in[1];
    const float* Wqis = (const float*)d_in[2];  const float* bqis = (const float*)d_in[3];
    const float* Wkis = (const float*)d_in[4];  const float* bkis = (const float*)d_in[5];
    const float* Wvis = (const float*)d_in[6];  const float* bvis = (const float*)d_in[7];
    const float* Wqcs = (const float*)d_in[8];  const float* bqcs = (const float*)d_in[9];
    const float* Wkcs = (const float*)d_in[10]; const float* bkcs = (const float*)d_in[11];
    const float* Wvcs = (const float*)d_in[12]; const float* bvcs = (const float*)d_in[13];
    float* out = (float*)d_out;

    cudaFuncSetAttribute(quant_proj_kernel,
                         cudaFuncAttributeMaxDynamicSharedMemorySize, 66560);
    cudaFuncSetAttribute(attn_kernel,
                         cudaFuncAttributeMaxDynamicSharedMemorySize, 98304);

    quant_proj_kernel<<<700, 128, 66560>>>(x, cb, out,
                                           Wqis, bqis, Wkis, bkis, Wvis, bvis,
                                           Wqcs, bqcs, Wkcs, bkcs, Wvcs, bvcs);
    attn_kernel<<<528, 128, 98304>>>(out);
    cs_combine_kernel<<<(N_ROWS * 16 + 255) / 256, 256>>>(out + 2 * N_ROWS * DIMV);
}

// round 10
// speedup vs baseline: 1.2366x; 1.2366x over previous
#include <cuda_runtime.h>
#include <cstdint>

#define N_ROWS 6400
#define DIMV 64
#define NUM_EMB 512
#define GROUP 100
#define NSPLIT 6
#define TILES_PER_SPLIT 17   // 5*17 + 15 = 100 key tiles of 64

// ---- scratch (no cudaMalloc allowed); +1024 pad so 64-row tile reads
// starting at row 6350 never go OOB ----
__device__ float g_qis[N_ROWS * DIMV + 1024];
__device__ float g_kis[N_ROWS * DIMV + 1024];
__device__ float g_vis[N_ROWS * DIMV + 1024];
__device__ float g_qcs[N_ROWS * DIMV + 1024];
__device__ float g_kcs[N_ROWS * DIMV + 1024];
__device__ float g_vcs[N_ROWS * DIMV + 1024];
__device__ float g_Opart[NSPLIT][N_ROWS * DIMV];
__device__ float g_mpart[NSPLIT][N_ROWS];
__device__ float g_lpart[NSPLIT][N_ROWS];

__device__ __forceinline__ uint32_t f2tf(float f) {
    uint32_t u;
    asm("cvt.rna.tf32.f32 %0, %1;" : "=r"(u) : "f"(f));
    return u;
}

__device__ __forceinline__ void mma_tf32(
    float* d,
    uint32_t a0, uint32_t a1, uint32_t a2, uint32_t a3,
    uint32_t b0, uint32_t b1)
{
    asm volatile(
        "mma.sync.aligned.m16n8k8.row.col.f32.tf32.tf32.f32 "
        "{%0,%1,%2,%3},{%4,%5,%6,%7},{%8,%9},{%0,%1,%2,%3};\n"
        : "+f"(d[0]), "+f"(d[1]), "+f"(d[2]), "+f"(d[3])
        : "r"(a0), "r"(a1), "r"(a2), "r"(a3), "r"(b0), "r"(b1));
}

// ============================================================
// Kernel 1: projections via tf32 MMA, 3-term hi/lo split.
// One (proj, 64-row block) per CTA: grid 600 x 128, 64KB+ dyn smem.
// W is [k][n] row-major -> stored in smem with the PV "V layout"
// (uint4 copy, 2*(key&3) swizzle) -> NO transpose, conflict-free
// B-fragment reads (pattern proven in the CS PV GEMM since R4).
// ============================================================
__global__ __launch_bounds__(128) void proj_kernel(
    const float* __restrict__ x,
    const float* __restrict__ W0, const float* __restrict__ b0,
    const float* __restrict__ W1, const float* __restrict__ b1,
    const float* __restrict__ W2, const float* __restrict__ b2,
    const float* __restrict__ W3, const float* __restrict__ b3,
    const float* __restrict__ W4, const float* __restrict__ b4,
    const float* __restrict__ W5, const float* __restrict__ b5)
{
    extern __shared__ uint32_t smbuf[];
    uint32_t* Fh = smbuf;             // 4096
    uint32_t* Fl = smbuf + 4096;      // 4096
    uint32_t* Wh = smbuf + 8192;      // 4096 (V-layout)
    uint32_t* Wl = smbuf + 12288;     // 4096
    float* bsm = (float*)(smbuf + 16384);  // 64

    int t = threadIdx.x;
    int wm = t >> 5, lane = t & 31;
    int g = lane >> 2, c4 = lane & 3;
    int rL = (wm * 16 + g) * 64;

    int p = blockIdx.x / 100;
    int rowBase = (blockIdx.x % 100) * 64;

    const float* Wlst[6] = {W0, W1, W2, W3, W4, W5};
    const float* blst[6] = {b0, b1, b2, b3, b4, b5};
    float* olst[6] = {g_qis, g_kis, g_vis, g_qcs, g_kcs, g_vcs};
    const float* W = Wlst[p];
    float* o = olst[p];

    // x rows -> A layout (row&7 swizzle), hi/lo split
    const float4* Xg = (const float4*)(x + rowBase * 64);
    const float4* Wg = (const float4*)W;
    for (int i = t; i < 1024; i += 128) {
        int row = i >> 4, j = i & 15;
        float4 f = Xg[i];
        uint32_t h0 = f2tf(f.x), h1 = f2tf(f.y), h2 = f2tf(f.z), h3 = f2tf(f.w);
        int ad = row * 64 + 4 * (j ^ (row & 7));
        *(uint4*)(Fh + ad) = make_uint4(h0, h1, h2, h3);
        *(uint4*)(Fl + ad) = make_uint4(
            f2tf(f.x - __uint_as_float(h0)), f2tf(f.y - __uint_as_float(h1)),
            f2tf(f.z - __uint_as_float(h2)), f2tf(f.w - __uint_as_float(h3)));
        // W row d=key -> V layout, hi/lo split
        float4 w = Wg[i];
        uint32_t wh0 = f2tf(w.x), wh1 = f2tf(w.y), wh2 = f2tf(w.z), wh3 = f2tf(w.w);
        int wd = row * 64 + 4 * (j ^ (2 * (row & 3)));
        *(uint4*)(Wh + wd) = make_uint4(wh0, wh1, wh2, wh3);
        *(uint4*)(Wl + wd) = make_uint4(
            f2tf(w.x - __uint_as_float(wh0)), f2tf(w.y - __uint_as_float(wh1)),
            f2tf(w.z - __uint_as_float(wh2)), f2tf(w.w - __uint_as_float(wh3)));
    }
    if (t < 64) bsm[t] = blst[p][t];
    __syncthreads();

    float S[8][4];
#pragma unroll
    for (int n = 0; n < 8; n++)
#pragma unroll
        for (int j = 0; j < 4; j++) S[n][j] = 0.f;

#pragma unroll
    for (int k0 = 0; k0 < 8; k0++) {
        int ch0 = 4 * ((2 * k0) ^ g);
        int ch1 = 4 * ((2 * k0 + 1) ^ g);
        uint32_t ah0 = Fh[rL + ch0 + c4], ah1 = Fh[rL + 512 + ch0 + c4];
        uint32_t ah2 = Fh[rL + ch1 + c4], ah3 = Fh[rL + 512 + ch1 + c4];
        uint32_t al0 = Fl[rL + ch0 + c4], al1 = Fl[rL + 512 + ch0 + c4];
        uint32_t al2 = Fl[rL + ch1 + c4], al3 = Fl[rL + 512 + ch1 + c4];
        int ky0 = (k0 * 8 + c4) * 64;
        int ky1 = ky0 + 256;
        int sw = 2 * c4;
#pragma unroll
        for (int n0 = 0; n0 < 8; n0++) {
            int ch = 4 * ((2 * n0 + (g >> 2)) ^ sw) + (g & 3);
            uint32_t bh0 = Wh[ky0 + ch];
            uint32_t bh1 = Wh[ky1 + ch];
            uint32_t bl0 = Wl[ky0 + ch];
            uint32_t bl1 = Wl[ky1 + ch];
            mma_tf32(S[n0], ah0, ah1, ah2, ah3, bh0, bh1);
            mma_tf32(S[n0], ah0, ah1, ah2, ah3, bl0, bl1);
            mma_tf32(S[n0], al0, al1, al2, al3, bh0, bh1);
        }
    }

    int rA = rowBase + wm * 16 + g;
#pragma unroll
    for (int n0 = 0; n0 < 8; n0++) {
        int col = n0 * 8 + 2 * c4;
        float bb0 = bsm[col], bb1 = bsm[col + 1];
        *(float2*)(o + rA * 64 + col) = make_float2(
            __uint_as_float(f2tf(S[n0][0] + bb0)),
            __uint_as_float(f2tf(S[n0][1] + bb1)));
        *(float2*)(o + (rA + 8) * 64 + col) = make_float2(
            __uint_as_float(f2tf(S[n0][2] + bb0)),
            __uint_as_float(f2tf(S[n0][3] + bb1)));
    }
}

// ============================================================
// Kernel 2: fused attention + quantization. 128 threads, 96KB dyn smem.
//   bid 0..299   : CS flash split-K (tf32 MMA), NSPLIT=6
//   bid 300..427 : IS attention (tf32 MMA, single 64-pad tile)
//   bid 428..527 : vector quantization (3-term tf32 MMA + argmin)
// ============================================================
__global__ __launch_bounds__(128) void attn_kernel(
    const float* __restrict__ x, const float* __restrict__ cb,
    float* __restrict__ out)
{
    extern __shared__ uint32_t smbuf[];
    int t = threadIdx.x;
    int wm = t >> 5, lane = t & 31;
    int g = lane >> 2, c4 = lane & 3;

    if (blockIdx.x >= 428) {
        // ================= quantization =================
        uint32_t* Fh = smbuf;            // 4096
        uint32_t* Fl = smbuf + 4096;     // 4096
        uint32_t* Ch = smbuf + 8192;     // 4096
        uint32_t* Cl = smbuf + 12288;    // 4096
        float* cns = (float*)(smbuf + 16384);  // 64

        int rBase = (blockIdx.x - 428) * 64;
        const float4* Fg = (const float4*)(x + rBase * 64);
        for (int i = t; i < 1024; i += 128) {
            int row = i >> 4, j = i & 15;
            float4 f = Fg[i];
            uint32_t h0 = f2tf(f.x), h1 = f2tf(f.y), h2 = f2tf(f.z), h3 = f2tf(f.w);
            int ad = row * 64 + 4 * (j ^ (row & 7));
            *(uint4*)(Fh + ad) = make_uint4(h0, h1, h2, h3);
            *(uint4*)(Fl + ad) = make_uint4(
                f2tf(f.x - __uint_as_float(h0)), f2tf(f.y - __uint_as_float(h1)),
                f2tf(f.z - __uint_as_float(h2)), f2tf(f.w - __uint_as_float(h3)));
        }

        float bA = 3.4e38f, bB = 3.4e38f;
        int iA = 0, iB = 0;
        int rL = (wm * 16 + g) * 64;

        for (int ct = 0; ct < 8; ct++) {
            __syncthreads();
            const float4* Cg = (const float4*)(cb + ct * 64 * 64);
            for (int i = t; i < 1024; i += 128) {
                int code = i >> 4, j = i & 15;
                float4 f = Cg[i];
                uint32_t h0 = f2tf(f.x), h1 = f2tf(f.y), h2 = f2tf(f.z), h3 = f2tf(f.w);
                int ad = code * 64 + 4 * (j ^ (code & 7));
                *(uint4*)(Ch + ad) = make_uint4(h0, h1, h2, h3);
                *(uint4*)(Cl + ad) = make_uint4(
                    f2tf(f.x - __uint_as_float(h0)), f2tf(f.y - __uint_as_float(h1)),
                    f2tf(f.z - __uint_as_float(h2)), f2tf(f.w - __uint_as_float(h3)));
            }
            __syncthreads();
            if (t < 64) {
                float s = 0.f;
#pragma unroll
                for (int j = 0; j < 16; j++) {
                    int ad = t * 64 + 4 * (j ^ (t & 7));
                    uint4 h = *(uint4*)(Ch + ad);
                    uint4 l = *(uint4*)(Cl + ad);
                    float v;
                    v = __uint_as_float(h.x) + __uint_as_float(l.x); s = fmaf(v, v, s);
                    v = __uint_as_float(h.y) + __uint_as_float(l.y); s = fmaf(v, v, s);
                    v = __uint_as_float(h.z) + __uint_as_float(l.z); s = fmaf(v, v, s);
                    v = __uint_as_float(h.w) + __uint_as_float(l.w); s = fmaf(v, v, s);
                }
                cns[t] = s;
            }
            __syncthreads();

            float S[8][4];
#pragma unroll
            for (int n = 0; n < 8; n++)
#pragma unroll
                for (int j = 0; j < 4; j++) S[n][j] = 0.f;

#pragma unroll
            for (int k0 = 0; k0 < 8; k0++) {
                int ch0 = 4 * ((2 * k0) ^ g);
                int ch1 = 4 * ((2 * k0 + 1) ^ g);
                uint32_t ah0 = Fh[rL + ch0 + c4], ah1 = Fh[rL + 512 + ch0 + c4];
                uint32_t ah2 = Fh[rL + ch1 + c4], ah3 = Fh[rL + 512 + ch1 + c4];
                uint32_t al0 = Fl[rL + ch0 + c4], al1 = Fl[rL + 512 + ch0 + c4];
                uint32_t al2 = Fl[rL + ch1 + c4], al3 = Fl[rL + 512 + ch1 + c4];
#pragma unroll
                for (int n0 = 0; n0 < 8; n0++) {
                    int key = n0 * 8 + g;
                    uint32_t bh0 = Ch[key * 64 + ch0 + c4];
                    uint32_t bh1 = Ch[key * 64 + ch1 + c4];
                    uint32_t bl0 = Cl[key * 64 + ch0 + c4];
                    uint32_t bl1 = Cl[key * 64 + ch1 + c4];
                    mma_tf32(S[n0], ah0, ah1, ah2, ah3, bh0, bh1);
                    mma_tf32(S[n0], ah0, ah1, ah2, ah3, bl0, bl1);
                    mma_tf32(S[n0], al0, al1, al2, al3, bh0, bh1);
                }
            }

#pragma unroll
            for (int n0 = 0; n0 < 8; n0++) {
                int c0 = n0 * 8 + 2 * c4;
                float cn0 = cns[c0], cn1 = cns[c0 + 1];
                int gi = ct * 64 + c0;
                float d;
                d = cn0 - 2.f * S[n0][0];
                if (d < bA || (d == bA && gi < iA)) { bA = d; iA = gi; }
                d = cn1 - 2.f * S[n0][1];
                if (d < bA || (d == bA && gi + 1 < iA)) { bA = d; iA = gi + 1; }
                d = cn0 - 2.f * S[n0][2];
                if (d < bB || (d == bB && gi < iB)) { bB = d; iB = gi; }
                d = cn1 - 2.f * S[n0][3];
                if (d < bB || (d == bB && gi + 1 < iB)) { bB = d; iB = gi + 1; }
            }
        }
#pragma unroll
        for (int off = 1; off <= 2; off <<= 1) {
            float ob; int oi;
            ob = __shfl_xor_sync(0xffffffffu, bA, off);
            oi = __shfl_xor_sync(0xffffffffu, iA, off);
            if (ob < bA || (ob == bA && oi < iA)) { bA = ob; iA = oi; }
            ob = __shfl_xor_sync(0xffffffffu, bB, off);
            oi = __shfl_xor_sync(0xffffffffu, iB, off);
            if (ob < bB || (ob == bB && oi < iB)) { bB = ob; iB = oi; }
        }
        int rA = rBase + wm * 16 + g;
        const float4* cbA = (const float4*)(cb + iA * 64);
        const float4* cbB = (const float4*)(cb + iB * 64);
        float4* oA = (float4*)(out + rA * 64);
        float4* oB = (float4*)(out + (rA + 8) * 64);
#pragma unroll
        for (int j = 0; j < 4; j++) {
            oA[c4 * 4 + j] = cbA[c4 * 4 + j];
            oB[c4 * 4 + j] = cbB[c4 * 4 + j];
        }
        return;
    }

    float* outZ = out + N_ROWS * DIMV;

    if (blockIdx.x >= 300) {
        // ================= IS attention =================
        uint32_t* Qs = smbuf;
        uint32_t* Ks = smbuf + 4096;
        uint32_t* Vs = smbuf + 8192;
        uint32_t* Ps = smbuf + 12288;
        int base = (blockIdx.x - 300) * 50;

        const uint4* Qg = (const uint4*)(g_kis + base * 64);
        const uint4* Kg = (const uint4*)(g_qis + base * 64);
        const uint4* Vg = (const uint4*)(g_vis + base * 64);
        for (int i = t; i < 1024; i += 128) {
            int row = i >> 4, j = i & 15;
            *(uint4*)(Qs + row * 64 + 4 * (j ^ (row & 7)))       = Qg[i];
            *(uint4*)(Ks + row * 64 + 4 * (j ^ (row & 7)))       = Kg[i];
            *(uint4*)(Vs + row * 64 + 4 * (j ^ (2 * (row & 3)))) = Vg[i];
        }
        __syncthreads();

        int rL = (wm * 16 + g) * 64;
        float S[8][4];
#pragma unroll
        for (int n = 0; n < 8; n++)
#pragma unroll
            for (int j = 0; j < 4; j++) S[n][j] = 0.f;

#pragma unroll
        for (int k0 = 0; k0 < 8; k0++) {
            int ch0 = 4 * ((2 * k0) ^ g);
            int ch1 = 4 * ((2 * k0 + 1) ^ g);
            uint32_t a0 = Qs[rL + ch0 + c4];
            uint32_t a1 = Qs[rL + 512 + ch0 + c4];
            uint32_t a2 = Qs[rL + ch1 + c4];
            uint32_t a3 = Qs[rL + 512 + ch1 + c4];
#pragma unroll
            for (int n0 = 0; n0 < 8; n0++) {
                int key = n0 * 8 + g;
                uint32_t b0 = Ks[key * 64 + ch0 + c4];
                uint32_t b1 = Ks[key * 64 + ch1 + c4];
                mma_tf32(S[n0], a0, a1, a2, a3, b0, b1);
            }
        }

        float rmA = -1e30f, rmB = -1e30f;
#pragma unroll
        for (int n0 = 0; n0 < 8; n0++) {
            int col0 = n0 * 8 + 2 * c4;
            if (col0 >= 50)     { S[n0][0] = -1e30f; S[n0][2] = -1e30f; }
            if (col0 + 1 >= 50) { S[n0][1] = -1e30f; S[n0][3] = -1e30f; }
            rmA = fmaxf(rmA, fmaxf(S[n0][0], S[n0][1]));
            rmB = fmaxf(rmB, fmaxf(S[n0][2], S[n0][3]));
        }
        rmA = fmaxf(rmA, __shfl_xor_sync(0xffffffffu, rmA, 1));
        rmA = fmaxf(rmA, __shfl_xor_sync(0xffffffffu, rmA, 2));
        rmB = fmaxf(rmB, __shfl_xor_sync(0xffffffffu, rmB, 1));
        rmB = fmaxf(rmB, __shfl_xor_sync(0xffffffffu, rmB, 2));

        float lsA = 0.f, lsB = 0.f;
#pragma unroll
        for (int n0 = 0; n0 < 8; n0++) {
            float pA0 = __expf(S[n0][0] - rmA);
            float pA1 = __expf(S[n0][1] - rmA);
            float pB0 = __expf(S[n0][2] - rmB);
            float pB1 = __expf(S[n0][3] - rmB);
            lsA += pA0 + pA1;
            lsB += pB0 + pB1;
            int chp = 4 * ((2 * n0 + (c4 >> 1)) ^ g) + ((2 * c4) & 3);
            *(uint2*)(Ps + rL + chp)       = make_uint2(f2tf(pA0), f2tf(pA1));
            *(uint2*)(Ps + rL + 512 + chp) = make_uint2(f2tf(pB0), f2tf(pB1));
        }
        lsA += __shfl_xor_sync(0xffffffffu, lsA, 1);
        lsA += __shfl_xor_sync(0xffffffffu, lsA, 2);
        lsB += __shfl_xor_sync(0xffffffffu, lsB, 1);
        lsB += __shfl_xor_sync(0xffffffffu, lsB, 2);
        __syncwarp();

        float O[8][4];
#pragma unroll
        for (int n = 0; n < 8; n++)
#pragma unroll
            for (int j = 0; j < 4; j++) O[n][j] = 0.f;

#pragma unroll
        for (int k0 = 0; k0 < 8; k0++) {
            int ch0 = 4 * ((2 * k0) ^ g);
            int ch1 = 4 * ((2 * k0 + 1) ^ g);
            uint32_t a0 = Ps[rL + ch0 + c4];
            uint32_t a1 = Ps[rL + 512 + ch0 + c4];
            uint32_t a2 = Ps[rL + ch1 + c4];
            uint32_t a3 = Ps[rL + 512 + ch1 + c4];
            int ky0 = (k0 * 8 + c4) * 64;
            int ky1 = ky0 + 256;
            int sw = 2 * c4;
#pragma unroll
            for (int n0 = 0; n0 < 8; n0++) {
                int ch = 4 * ((2 * n0 + (g >> 2)) ^ sw) + (g & 3);
                uint32_t b0 = Vs[ky0 + ch];
                uint32_t b1 = Vs[ky1 + ch];
                mma_tf32(O[n0], a0, a1, a2, a3, b0, b1);
            }
        }

        float invA = 1.f / lsA, invB = 1.f / lsB;
        int r0 = wm * 16 + g;
#pragma unroll
        for (int n0 = 0; n0 < 8; n0++) {
            int col = n0 * 8 + 2 * c4;
            if (r0 < 50)
                *(float2*)(outZ + (base + r0) * 64 + col) =
                    make_float2(O[n0][0] * invA, O[n0][1] * invA);
            if (r0 + 8 < 50)
                *(float2*)(outZ + (base + r0 + 8) * 64 + col) =
                    make_float2(O[n0][2] * invB, O[n0][3] * invB);
        }
        return;
    }

    // ================= CS attention (flash + split-K) =================
    uint32_t* Qs = smbuf;            // 8192 words
    uint32_t* Ks = smbuf + 8192;     // 4096
    uint32_t* Vs = smbuf + 12288;    // 4096
    uint32_t* Ps = smbuf + 16384;    // 8192

    int bid = blockIdx.x;
    int qt = bid / NSPLIT, sp = bid % NSPLIT;
    int qBase = qt * 128;

    {
        const uint4* Qg = (const uint4*)(g_kcs + qBase * 64);
        for (int i = t; i < 2048; i += 128) {
            int row = i >> 4, j = i & 15;
            *(uint4*)(Qs + row * 64 + 4 * (j ^ (row & 7))) = Qg[i];
        }
    }

    float S[2][8][4];
    float O[2][8][4];
#pragma unroll
    for (int b = 0; b < 2; b++)
#pragma unroll
        for (int n = 0; n < 8; n++)
#pragma unroll
            for (int j = 0; j < 4; j++) O[b][n][j] = 0.f;

    float mv[4], lv[4];
    int qsamp[4];
#pragma unroll
    for (int s = 0; s < 4; s++) {
        mv[s] = -1e30f; lv[s] = 0.f;
        int row = qBase + wm * 32 + (s >> 1) * 16 + (s & 1) * 8 + g;
        qsamp[s] = row / GROUP;
    }

    int ktStart = sp * TILES_PER_SPLIT;
    int ktEnd = ktStart + TILES_PER_SPLIT;
    if (ktEnd > 100) ktEnd = 100;

    for (int kt = ktStart; kt < ktEnd; kt++) {
        __syncthreads();
        int kBase = kt * 64;
        {
            const uint4* Kg = (const uint4*)(g_qcs + kBase * 64);
            const uint4* Vg = (const uint4*)(g_vcs + kBase * 64);
            for (int i = t; i < 1024; i += 128) {
                int key = i >> 4, j = i & 15;
                *(uint4*)(Ks + key * 64 + 4 * (j ^ (key & 7)))       = Kg[i];
                *(uint4*)(Vs + key * 64 + 4 * (j ^ (2 * (key & 3)))) = Vg[i];
            }
        }
        __syncthreads();

#pragma unroll
        for (int b = 0; b < 2; b++)
#pragma unroll
            for (int n = 0; n < 8; n++)
#pragma unroll
                for (int j = 0; j < 4; j++) S[b][n][j] = 0.f;

#pragma unroll
        for (int k0 = 0; k0 < 8; k0++) {
            int ch0 = 4 * ((2 * k0) ^ g);
            int ch1 = 4 * ((2 * k0 + 1) ^ g);
            uint32_t a[2][4];
#pragma unroll
            for (int b = 0; b < 2; b++) {
                int rL = (wm * 32 + b * 16 + g) * 64;
                a[b][0] = Qs[rL + ch0 + c4];
                a[b][1] = Qs[rL + 512 + ch0 + c4];
                a[b][2] = Qs[rL + ch1 + c4];
                a[b][3] = Qs[rL + 512 + ch1 + c4];
            }
#pragma unroll
            for (int n0 = 0; n0 < 8; n0++) {
                int key = n0 * 8 + g;
                uint32_t b0 = Ks[key * 64 + ch0 + c4];
                uint32_t b1 = Ks[key * 64 + ch1 + c4];
                mma_tf32(S[0][n0], a[0][0], a[0][1], a[0][2], a[0][3], b0, b1);
                mma_tf32(S[1][n0], a[1][0], a[1][1], a[1][2], a[1][3], b0, b1);
            }
        }

        float rm[4] = {-1e30f, -1e30f, -1e30f, -1e30f};
#pragma unroll
        for (int n0 = 0; n0 < 8; n0++) {
            int col0 = kBase + n0 * 8 + 2 * c4;
            int cs0 = col0 / GROUP, cs1 = (col0 + 1) / GROUP;
#pragma unroll
            for (int s = 0; s < 4; s++) {
                int b = s >> 1, h = s & 1;
                if (cs0 == qsamp[s]) S[b][n0][2 * h]     = -1e30f;
                if (cs1 == qsamp[s]) S[b][n0][2 * h + 1] = -1e30f;
                rm[s] = fmaxf(rm[s], fmaxf(S[b][n0][2 * h], S[b][n0][2 * h + 1]));
            }
        }
        float corr[4];
#pragma unroll
        for (int s = 0; s < 4; s++) {
            rm[s] = fmaxf(rm[s], __shfl_xor_sync(0xffffffffu, rm[s], 1));
            rm[s] = fmaxf(rm[s], __shfl_xor_sync(0xffffffffu, rm[s], 2));
            float mn = fmaxf(mv[s], rm[s]);
            corr[s] = __expf(mv[s] - mn);
            mv[s] = mn;
        }
        float ls[4] = {0.f, 0.f, 0.f, 0.f};
#pragma unroll
        for (int n0 = 0; n0 < 8; n0++) {
            int chp = 4 * ((2 * n0 + (c4 >> 1)) ^ g) + ((2 * c4) & 3);
#pragma unroll
            for (int s = 0; s < 4; s++) {
                int b = s >> 1, h = s & 1;
                float p0 = __expf(S[b][n0][2 * h]     - mv[s]);
                float p1 = __expf(S[b][n0][2 * h + 1] - mv[s]);
                ls[s] += p0 + p1;
                int row = wm * 32 + b * 16 + h * 8 + g;
                *(uint2*)(Ps + row * 64 + chp) = make_uint2(f2tf(p0), f2tf(p1));
            }
        }
#pragma unroll
        for (int s = 0; s < 4; s++) {
            ls[s] += __shfl_xor_sync(0xffffffffu, ls[s], 1);
            ls[s] += __shfl_xor_sync(0xffffffffu, ls[s], 2);
            lv[s] = lv[s] * corr[s] + ls[s];
            int b = s >> 1, h = s & 1;
#pragma unroll
            for (int n0 = 0; n0 < 8; n0++) {
                O[b][n0][2 * h]     *= corr[s];
                O[b][n0][2 * h + 1] *= corr[s];
            }
        }
        __syncwarp();

#pragma unroll
        for (int k0 = 0; k0 < 8; k0++) {
            int ch0 = 4 * ((2 * k0) ^ g);
            int ch1 = 4 * ((2 * k0 + 1) ^ g);
            uint32_t a[2][4];
#pragma unroll
            for (int b = 0; b < 2; b++) {
                int rL = (wm * 32 + b * 16 + g) * 64;
                a[b][0] = Ps[rL + ch0 + c4];
                a[b][1] = Ps[rL + 512 + ch0 + c4];
                a[b][2] = Ps[rL + ch1 + c4];
                a[b][3] = Ps[rL + 512 + ch1 + c4];
            }
            int ky0 = (k0 * 8 + c4) * 64;
            int ky1 = ky0 + 256;
            int sw = 2 * c4;
#pragma unroll
            for (int n0 = 0; n0 < 8; n0++) {
                int ch = 4 * ((2 * n0 + (g >> 2)) ^ sw) + (g & 3);
                uint32_t b0 = Vs[ky0 + ch];
                uint32_t b1 = Vs[ky1 + ch];
                mma_tf32(O[0][n0], a[0][0], a[0][1], a[0][2], a[0][3], b0, b1);
                mma_tf32(O[1][n0], a[1][0], a[1][1], a[1][2], a[1][3], b0, b1);
            }
        }
    }

    float* Op = g_Opart[sp];
#pragma unroll
    for (int b = 0; b < 2; b++) {
        int rowA = qBase + wm * 32 + b * 16 + g;
#pragma unroll
        for (int n0 = 0; n0 < 8; n0++) {
            int col = n0 * 8 + 2 * c4;
            *(float2*)(Op + rowA * 64 + col)       = make_float2(O[b][n0][0], O[b][n0][1]);
            *(float2*)(Op + (rowA + 8) * 64 + col) = make_float2(O[b][n0][2], O[b][n0][3]);
        }
    }
    if (c4 == 0) {
#pragma unroll
        for (int s = 0; s < 4; s++) {
            int row = qBase + wm * 32 + (s >> 1) * 16 + (s & 1) * 8 + g;
            g_mpart[sp][row] = mv[s];
            g_lpart[sp][row] = lv[s];
        }
    }
}

// ============================================================
// Kernel 3: combine split-K partials.
// ============================================================
__global__ __launch_bounds__(256) void cs_combine_kernel(float* __restrict__ outX)
{
    int gidx = blockIdx.x * 256 + threadIdx.x;
    int row = gidx >> 4;
    int e4 = gidx & 15;
    if (row >= N_ROWS) return;

    float m[NSPLIT];
    float M = -3.4e38f;
#pragma unroll
    for (int s = 0; s < NSPLIT; s++) { m[s] = g_mpart[s][row]; M = fmaxf(M, m[s]); }
    float wgt[NSPLIT];
    float denom = 0.f;
#pragma unroll
    for (int s = 0; s < NSPLIT; s++) {
        wgt[s] = __expf(m[s] - M);
        denom += wgt[s] * g_lpart[s][row];
    }
    float inv = 1.f / denom;

    float4 o = {0.f, 0.f, 0.f, 0.f};
#pragma unroll
    for (int s = 0; s < NSPLIT; s++) {
        float4 a = ((const float4*)g_Opart[s])[row * 16 + e4];
        o.x = fmaf(a.x, wgt[s], o.x);
        o.y = fmaf(a.y, wgt[s], o.y);
        o.z = fmaf(a.z, wgt[s], o.z);
        o.w = fmaf(a.w, wgt[s], o.w);
    }
    o.x *= inv; o.y *= inv; o.z *= inv; o.w *= inv;
    ((float4*)outX)[row * 16 + e4] = o;
}

// ============================================================
extern "C" void kernel_launch(void* const* d_in, const int* in_sizes, int n_in,
                              void* d_out, int out_size)
{
    const float* x    = (const float*)d_in[0];
    const float* cb   = (const float*)d_in[1];
    const float* Wqis = (const float*)d_in[2];  const float* bqis = (const float*)d_in[3];
    const float* Wkis = (const float*)d_in[4];  const float* bkis = (const float*)d_in[5];
    const float* Wvis = (const float*)d_in[6];  const float* bvis = (const float*)d_in[7];
    const float* Wqcs = (const float*)d_in[8];  const float* bqcs = (const float*)d_in[9];
    const float* Wkcs = (const float*)d_in[10]; const float* bkcs = (const float*)d_in[11];
    const float* Wvcs = (const float*)d_in[12]; const float* bvcs = (const float*)d_in[13];
    float* out = (float*)d_out;

    cudaFuncSetAttribute(proj_kernel,
                         cudaFuncAttributeMaxDynamicSharedMemorySize, 66560);
    cudaFuncSetAttribute(attn_kernel,
                         cudaFuncAttributeMaxDynamicSharedMemorySize, 98304);

    proj_kernel<<<600, 128, 66560>>>(x, Wqis, bqis, Wkis, bkis, Wvis, bvis,
                                     Wqcs, bqcs, Wkcs, bkcs, Wvcs, bvcs);
    attn_kernel<<<528, 128, 98304>>>(x, cb, out);
    cs_combine_kernel<<<(N_ROWS * 16 + 255) / 256, 256>>>(out + 2 * N_ROWS * DIMV);
}

// round 11
// speedup vs baseline: 1.2757x; 1.0317x over previous
#include <cuda_runtime.h>
#include <cstdint>

#define N_ROWS 6400
#define DIMV 64
#define NUM_EMB 512
#define GROUP 100
#define NSPLIT 6
#define TILES_PER_SPLIT 17   // 5*17 + 15 = 100 key tiles of 64

// ---- scratch (no cudaMalloc allowed); +1024 pad so 64-row tile reads
// starting at row 6350 never go OOB ----
__device__ float g_qis[N_ROWS * DIMV + 1024];
__device__ float g_kis[N_ROWS * DIMV + 1024];
__device__ float g_vis[N_ROWS * DIMV + 1024];
__device__ float g_qcs[N_ROWS * DIMV + 1024];
__device__ float g_kcs[N_ROWS * DIMV + 1024];
__device__ float g_vcs[N_ROWS * DIMV + 1024];
__device__ float g_Opart[NSPLIT][N_ROWS * DIMV];
__device__ float g_mpart[NSPLIT][N_ROWS];
__device__ float g_lpart[NSPLIT][N_ROWS];

__device__ __forceinline__ uint32_t f2tf(float f) {
    uint32_t u;
    asm("cvt.rna.tf32.f32 %0, %1;" : "=r"(u) : "f"(f));
    return u;
}

__device__ __forceinline__ void mma_tf32(
    float* d,
    uint32_t a0, uint32_t a1, uint32_t a2, uint32_t a3,
    uint32_t b0, uint32_t b1)
{
    asm volatile(
        "mma.sync.aligned.m16n8k8.row.col.f32.tf32.tf32.f32 "
        "{%0,%1,%2,%3},{%4,%5,%6,%7},{%8,%9},{%0,%1,%2,%3};\n"
        : "+f"(d[0]), "+f"(d[1]), "+f"(d[2]), "+f"(d[3])
        : "r"(a0), "r"(a1), "r"(a2), "r"(a3), "r"(b0), "r"(b1));
}

// ============================================================
// Kernel 1: projections via tf32 MMA, 3-term hi/lo split.
// 256 threads, 128 rows per CTA (8 warps x one m16 block),
// grid 300 = 6 proj x 50 blocks -> ~1 wave at 2 CTAs/SM.
// W is [k][n] row-major in the PV "V layout" (no transpose,
// conflict-free B reads, pattern proven since R4).
// ============================================================
__global__ __launch_bounds__(256) void proj_kernel(
    const float* __restrict__ x,
    const float* __restrict__ W0, const float* __restrict__ b0,
    const float* __restrict__ W1, const float* __restrict__ b1,
    const float* __restrict__ W2, const float* __restrict__ b2,
    const float* __restrict__ W3, const float* __restrict__ b3,
    const float* __restrict__ W4, const float* __restrict__ b4,
    const float* __restrict__ W5, const float* __restrict__ b5)
{
    extern __shared__ uint32_t smbuf[];
    uint32_t* Fh = smbuf;              // 8192 (128 rows)
    uint32_t* Fl = smbuf + 8192;       // 8192
    uint32_t* Wh = smbuf + 16384;      // 4096 (V-layout)
    uint32_t* Wl = smbuf + 20480;      // 4096
    float* bsm = (float*)(smbuf + 24576);  // 64

    int t = threadIdx.x;
    int wm = t >> 5, lane = t & 31;    // wm 0..7
    int g = lane >> 2, c4 = lane & 3;
    int rL = (wm * 16 + g) * 64;

    int p = blockIdx.x / 50;
    int rowBase = (blockIdx.x % 50) * 128;

    const float* Wlst[6] = {W0, W1, W2, W3, W4, W5};
    const float* blst[6] = {b0, b1, b2, b3, b4, b5};
    float* olst[6] = {g_qis, g_kis, g_vis, g_qcs, g_kcs, g_vcs};
    const float* W = Wlst[p];
    float* o = olst[p];

    // x rows (128) -> A layout (row&7 swizzle), hi/lo split
    const float4* Xg = (const float4*)(x + rowBase * 64);
    for (int i = t; i < 2048; i += 256) {
        int row = i >> 4, j = i & 15;
        float4 f = Xg[i];
        uint32_t h0 = f2tf(f.x), h1 = f2tf(f.y), h2 = f2tf(f.z), h3 = f2tf(f.w);
        int ad = row * 64 + 4 * (j ^ (row & 7));
        *(uint4*)(Fh + ad) = make_uint4(h0, h1, h2, h3);
        *(uint4*)(Fl + ad) = make_uint4(
            f2tf(f.x - __uint_as_float(h0)), f2tf(f.y - __uint_as_float(h1)),
            f2tf(f.z - __uint_as_float(h2)), f2tf(f.w - __uint_as_float(h3)));
    }
    // W rows (64, k-major) -> V layout, hi/lo split
    const float4* Wg = (const float4*)W;
    for (int i = t; i < 1024; i += 256) {
        int row = i >> 4, j = i & 15;
        float4 w = Wg[i];
        uint32_t wh0 = f2tf(w.x), wh1 = f2tf(w.y), wh2 = f2tf(w.z), wh3 = f2tf(w.w);
        int wd = row * 64 + 4 * (j ^ (2 * (row & 3)));
        *(uint4*)(Wh + wd) = make_uint4(wh0, wh1, wh2, wh3);
        *(uint4*)(Wl + wd) = make_uint4(
            f2tf(w.x - __uint_as_float(wh0)), f2tf(w.y - __uint_as_float(wh1)),
            f2tf(w.z - __uint_as_float(wh2)), f2tf(w.w - __uint_as_float(wh3)));
    }
    if (t < 64) bsm[t] = blst[p][t];
    __syncthreads();

    float S[8][4];
#pragma unroll
    for (int n = 0; n < 8; n++)
#pragma unroll
        for (int j = 0; j < 4; j++) S[n][j] = 0.f;

#pragma unroll
    for (int k0 = 0; k0 < 8; k0++) {
        int ch0 = 4 * ((2 * k0) ^ g);
        int ch1 = 4 * ((2 * k0 + 1) ^ g);
        uint32_t ah0 = Fh[rL + ch0 + c4], ah1 = Fh[rL + 512 + ch0 + c4];
        uint32_t ah2 = Fh[rL + ch1 + c4], ah3 = Fh[rL + 512 + ch1 + c4];
        uint32_t al0 = Fl[rL + ch0 + c4], al1 = Fl[rL + 512 + ch0 + c4];
        uint32_t al2 = Fl[rL + ch1 + c4], al3 = Fl[rL + 512 + ch1 + c4];
        int ky0 = (k0 * 8 + c4) * 64;
        int ky1 = ky0 + 256;
        int sw = 2 * c4;
#pragma unroll
        for (int n0 = 0; n0 < 8; n0++) {
            int ch = 4 * ((2 * n0 + (g >> 2)) ^ sw) + (g & 3);
            uint32_t bh0 = Wh[ky0 + ch];
            uint32_t bh1 = Wh[ky1 + ch];
            uint32_t bl0 = Wl[ky0 + ch];
            uint32_t bl1 = Wl[ky1 + ch];
            mma_tf32(S[n0], ah0, ah1, ah2, ah3, bh0, bh1);
            mma_tf32(S[n0], ah0, ah1, ah2, ah3, bl0, bl1);
            mma_tf32(S[n0], al0, al1, al2, al3, bh0, bh1);
        }
    }

    int rA = rowBase + wm * 16 + g;
#pragma unroll
    for (int n0 = 0; n0 < 8; n0++) {
        int col = n0 * 8 + 2 * c4;
        float bb0 = bsm[col], bb1 = bsm[col + 1];
        *(float2*)(o + rA * 64 + col) = make_float2(
            __uint_as_float(f2tf(S[n0][0] + bb0)),
            __uint_as_float(f2tf(S[n0][1] + bb1)));
        *(float2*)(o + (rA + 8) * 64 + col) = make_float2(
            __uint_as_float(f2tf(S[n0][2] + bb0)),
            __uint_as_float(f2tf(S[n0][3] + bb1)));
    }
}

// ============================================================
// Kernel 2: fused attention + quantization. 128 threads, 96KB dyn smem.
//   bid 0..299   : CS flash split-K (tf32 MMA), NSPLIT=6
//   bid 300..427 : IS attention (tf32 MMA, single 64-pad tile)
//   bid 428..527 : vector quantization (3-term tf32 MMA + argmin)
// ============================================================
__global__ __launch_bounds__(128) void attn_kernel(
    const float* __restrict__ x, const float* __restrict__ cb,
    float* __restrict__ out)
{
    extern __shared__ uint32_t smbuf[];
    int t = threadIdx.x;
    int wm = t >> 5, lane = t & 31;
    int g = lane >> 2, c4 = lane & 3;

    if (blockIdx.x >= 428) {
        // ================= quantization =================
        uint32_t* Fh = smbuf;            // 4096
        uint32_t* Fl = smbuf + 4096;     // 4096
        uint32_t* Ch = smbuf + 8192;     // 4096
        uint32_t* Cl = smbuf + 12288;    // 4096
        float* cns = (float*)(smbuf + 16384);  // 64

        int rBase = (blockIdx.x - 428) * 64;
        const float4* Fg = (const float4*)(x + rBase * 64);
        for (int i = t; i < 1024; i += 128) {
            int row = i >> 4, j = i & 15;
            float4 f = Fg[i];
            uint32_t h0 = f2tf(f.x), h1 = f2tf(f.y), h2 = f2tf(f.z), h3 = f2tf(f.w);
            int ad = row * 64 + 4 * (j ^ (row & 7));
            *(uint4*)(Fh + ad) = make_uint4(h0, h1, h2, h3);
            *(uint4*)(Fl + ad) = make_uint4(
                f2tf(f.x - __uint_as_float(h0)), f2tf(f.y - __uint_as_float(h1)),
                f2tf(f.z - __uint_as_float(h2)), f2tf(f.w - __uint_as_float(h3)));
        }

        float bA = 3.4e38f, bB = 3.4e38f;
        int iA = 0, iB = 0;
        int rL = (wm * 16 + g) * 64;

        for (int ct = 0; ct < 8; ct++) {
            __syncthreads();
            const float4* Cg = (const float4*)(cb + ct * 64 * 64);
            for (int i = t; i < 1024; i += 128) {
                int code = i >> 4, j = i & 15;
                float4 f = Cg[i];
                uint32_t h0 = f2tf(f.x), h1 = f2tf(f.y), h2 = f2tf(f.z), h3 = f2tf(f.w);
                int ad = code * 64 + 4 * (j ^ (code & 7));
                *(uint4*)(Ch + ad) = make_uint4(h0, h1, h2, h3);
                *(uint4*)(Cl + ad) = make_uint4(
                    f2tf(f.x - __uint_as_float(h0)), f2tf(f.y - __uint_as_float(h1)),
                    f2tf(f.z - __uint_as_float(h2)), f2tf(f.w - __uint_as_float(h3)));
            }
            __syncthreads();
            if (t < 64) {
                float s = 0.f;
#pragma unroll
                for (int j = 0; j < 16; j++) {
                    int ad = t * 64 + 4 * (j ^ (t & 7));
                    uint4 h = *(uint4*)(Ch + ad);
                    uint4 l = *(uint4*)(Cl + ad);
                    float v;
                    v = __uint_as_float(h.x) + __uint_as_float(l.x); s = fmaf(v, v, s);
                    v = __uint_as_float(h.y) + __uint_as_float(l.y); s = fmaf(v, v, s);
                    v = __uint_as_float(h.z) + __uint_as_float(l.z); s = fmaf(v, v, s);
                    v = __uint_as_float(h.w) + __uint_as_float(l.w); s = fmaf(v, v, s);
                }
                cns[t] = s;
            }
            __syncthreads();

            float S[8][4];
#pragma unroll
            for (int n = 0; n < 8; n++)
#pragma unroll
                for (int j = 0; j < 4; j++) S[n][j] = 0.f;

#pragma unroll
            for (int k0 = 0; k0 < 8; k0++) {
                int ch0 = 4 * ((2 * k0) ^ g);
                int ch1 = 4 * ((2 * k0 + 1) ^ g);
                uint32_t ah0 = Fh[rL + ch0 + c4], ah1 = Fh[rL + 512 + ch0 + c4];
                uint32_t ah2 = Fh[rL + ch1 + c4], ah3 = Fh[rL + 512 + ch1 + c4];
                uint32_t al0 = Fl[rL + ch0 + c4], al1 = Fl[rL + 512 + ch0 + c4];
                uint32_t al2 = Fl[rL + ch1 + c4], al3 = Fl[rL + 512 + ch1 + c4];
#pragma unroll
                for (int n0 = 0; n0 < 8; n0++) {
                    int key = n0 * 8 + g;
                    uint32_t bh0 = Ch[key * 64 + ch0 + c4];
                    uint32_t bh1 = Ch[key * 64 + ch1 + c4];
                    uint32_t bl0 = Cl[key * 64 + ch0 + c4];
                    uint32_t bl1 = Cl[key * 64 + ch1 + c4];
                    mma_tf32(S[n0], ah0, ah1, ah2, ah3, bh0, bh1);
                    mma_tf32(S[n0], ah0, ah1, ah2, ah3, bl0, bl1);
                    mma_tf32(S[n0], al0, al1, al2, al3, bh0, bh1);
                }
            }

#pragma unroll
            for (int n0 = 0; n0 < 8; n0++) {
                int c0 = n0 * 8 + 2 * c4;
                float cn0 = cns[c0], cn1 = cns[c0 + 1];
                int gi = ct * 64 + c0;
                float d;
                d = cn0 - 2.f * S[n0][0];
                if (d < bA || (d == bA && gi < iA)) { bA = d; iA = gi; }
                d = cn1 - 2.f * S[n0][1];
                if (d < bA || (d == bA && gi + 1 < iA)) { bA = d; iA = gi + 1; }
                d = cn0 - 2.f * S[n0][2];
                if (d < bB || (d == bB && gi < iB)) { bB = d; iB = gi; }
                d = cn1 - 2.f * S[n0][3];
                if (d < bB || (d == bB && gi + 1 < iB)) { bB = d; iB = gi + 1; }
            }
        }
#pragma unroll
        for (int off = 1; off <= 2; off <<= 1) {
            float ob; int oi;
            ob = __shfl_xor_sync(0xffffffffu, bA, off);
            oi = __shfl_xor_sync(0xffffffffu, iA, off);
            if (ob < bA || (ob == bA && oi < iA)) { bA = ob; iA = oi; }
            ob = __shfl_xor_sync(0xffffffffu, bB, off);
            oi = __shfl_xor_sync(0xffffffffu, iB, off);
            if (ob < bB || (ob == bB && oi < iB)) { bB = ob; iB = oi; }
        }
        int rA = rBase + wm * 16 + g;
        const float4* cbA = (const float4*)(cb + iA * 64);
        const float4* cbB = (const float4*)(cb + iB * 64);
        float4* oA = (float4*)(out + rA * 64);
        float4* oB = (float4*)(out + (rA + 8) * 64);
#pragma unroll
        for (int j = 0; j < 4; j++) {
            oA[c4 * 4 + j] = cbA[c4 * 4 + j];
            oB[c4 * 4 + j] = cbB[c4 * 4 + j];
        }
        return;
    }

    float* outZ = out + N_ROWS * DIMV;

    if (blockIdx.x >= 300) {
        // ================= IS attention =================
        uint32_t* Qs = smbuf;
        uint32_t* Ks = smbuf + 4096;
        uint32_t* Vs = smbuf + 8192;
        uint32_t* Ps = smbuf + 12288;
        int base = (blockIdx.x - 300) * 50;

        const uint4* Qg = (const uint4*)(g_kis + base * 64);
        const uint4* Kg = (const uint4*)(g_qis + base * 64);
        const uint4* Vg = (const uint4*)(g_vis + base * 64);
        for (int i = t; i < 1024; i += 128) {
            int row = i >> 4, j = i & 15;
            *(uint4*)(Qs + row * 64 + 4 * (j ^ (row & 7)))       = Qg[i];
            *(uint4*)(Ks + row * 64 + 4 * (j ^ (row & 7)))       = Kg[i];
            *(uint4*)(Vs + row * 64 + 4 * (j ^ (2 * (row & 3)))) = Vg[i];
        }
        __syncthreads();

        int rL = (wm * 16 + g) * 64;
        float S[8][4];
#pragma unroll
        for (int n = 0; n < 8; n++)
#pragma unroll
            for (int j = 0; j < 4; j++) S[n][j] = 0.f;

#pragma unroll
        for (int k0 = 0; k0 < 8; k0++) {
            int ch0 = 4 * ((2 * k0) ^ g);
            int ch1 = 4 * ((2 * k0 + 1) ^ g);
            uint32_t a0 = Qs[rL + ch0 + c4];
            uint32_t a1 = Qs[rL + 512 + ch0 + c4];
            uint32_t a2 = Qs[rL + ch1 + c4];
            uint32_t a3 = Qs[rL + 512 + ch1 + c4];
#pragma unroll
            for (int n0 = 0; n0 < 8; n0++) {
                int key = n0 * 8 + g;
                uint32_t b0 = Ks[key * 64 + ch0 + c4];
                uint32_t b1 = Ks[key * 64 + ch1 + c4];
                mma_tf32(S[n0], a0, a1, a2, a3, b0, b1);
            }
        }

        float rmA = -1e30f, rmB = -1e30f;
#pragma unroll
        for (int n0 = 0; n0 < 8; n0++) {
            int col0 = n0 * 8 + 2 * c4;
            if (col0 >= 50)     { S[n0][0] = -1e30f; S[n0][2] = -1e30f; }
            if (col0 + 1 >= 50) { S[n0][1] = -1e30f; S[n0][3] = -1e30f; }
            rmA = fmaxf(rmA, fmaxf(S[n0][0], S[n0][1]));
            rmB = fmaxf(rmB, fmaxf(S[n0][2], S[n0][3]));
        }
        rmA = fmaxf(rmA, __shfl_xor_sync(0xffffffffu, rmA, 1));
        rmA = fmaxf(rmA, __shfl_xor_sync(0xffffffffu, rmA, 2));
        rmB = fmaxf(rmB, __shfl_xor_sync(0xffffffffu, rmB, 1));
        rmB = fmaxf(rmB, __shfl_xor_sync(0xffffffffu, rmB, 2));

        float lsA = 0.f, lsB = 0.f;
#pragma unroll
        for (int n0 = 0; n0 < 8; n0++) {
            float pA0 = __expf(S[n0][0] - rmA);
            float pA1 = __expf(S[n0][1] - rmA);
            float pB0 = __expf(S[n0][2] - rmB);
            float pB1 = __expf(S[n0][3] - rmB);
            lsA += pA0 + pA1;
            lsB += pB0 + pB1;
            int chp = 4 * ((2 * n0 + (c4 >> 1)) ^ g) + ((2 * c4) & 3);
            *(uint2*)(Ps + rL + chp)       = make_uint2(f2tf(pA0), f2tf(pA1));
            *(uint2*)(Ps + rL + 512 + chp) = make_uint2(f2tf(pB0), f2tf(pB1));
        }
        lsA += __shfl_xor_sync(0xffffffffu, lsA, 1);
        lsA += __shfl_xor_sync(0xffffffffu, lsA, 2);
        lsB += __shfl_xor_sync(0xffffffffu, lsB, 1);
        lsB += __shfl_xor_sync(0xffffffffu, lsB, 2);
        __syncwarp();

        float O[8][4];
#pragma unroll
        for (int n = 0; n < 8; n++)
#pragma unroll
            for (int j = 0; j < 4; j++) O[n][j] = 0.f;

#pragma unroll
        for (int k0 = 0; k0 < 8; k0++) {
            int ch0 = 4 * ((2 * k0) ^ g);
            int ch1 = 4 * ((2 * k0 + 1) ^ g);
            uint32_t a0 = Ps[rL + ch0 + c4];
            uint32_t a1 = Ps[rL + 512 + ch0 + c4];
            uint32_t a2 = Ps[rL + ch1 + c4];
            uint32_t a3 = Ps[rL + 512 + ch1 + c4];
            int ky0 = (k0 * 8 + c4) * 64;
            int ky1 = ky0 + 256;
            int sw = 2 * c4;
#pragma unroll
            for (int n0 = 0; n0 < 8; n0++) {
                int ch = 4 * ((2 * n0 + (g >> 2)) ^ sw) + (g & 3);
                uint32_t b0 = Vs[ky0 + ch];
                uint32_t b1 = Vs[ky1 + ch];
                mma_tf32(O[n0], a0, a1, a2, a3, b0, b1);
            }
        }

        float invA = 1.f / lsA, invB = 1.f / lsB;
        int r0 = wm * 16 + g;
#pragma unroll
        for (int n0 = 0; n0 < 8; n0++) {
            int col = n0 * 8 + 2 * c4;
            if (r0 < 50)
                *(float2*)(outZ + (base + r0) * 64 + col) =
                    make_float2(O[n0][0] * invA, O[n0][1] * invA);
            if (r0 + 8 < 50)
                *(float2*)(outZ + (base + r0 + 8) * 64 + col) =
                    make_float2(O[n0][2] * invB, O[n0][3] * invB);
        }
        return;
    }

    // ================= CS attention (flash + split-K) =================
    uint32_t* Qs = smbuf;            // 8192 words
    uint32_t* Ks = smbuf + 8192;     // 4096
    uint32_t* Vs = smbuf + 12288;    // 4096
    uint32_t* Ps = smbuf + 16384;    // 8192

    int bid = blockIdx.x;
    int qt = bid / NSPLIT, sp = bid % NSPLIT;
    int qBase = qt * 128;

    {
        const uint4* Qg = (const uint4*)(g_kcs + qBase * 64);
        for (int i = t; i < 2048; i += 128) {
            int row = i >> 4, j = i & 15;
            *(uint4*)(Qs + row * 64 + 4 * (j ^ (row & 7))) = Qg[i];
        }
    }

    float S[2][8][4];
    float O[2][8][4];
#pragma unroll
    for (int b = 0; b < 2; b++)
#pragma unroll
        for (int n = 0; n < 8; n++)
#pragma unroll
            for (int j = 0; j < 4; j++) O[b][n][j] = 0.f;

    float mv[4], lv[4];
    int qsamp[4];
#pragma unroll
    for (int s = 0; s < 4; s++) {
        mv[s] = -1e30f; lv[s] = 0.f;
        int row = qBase + wm * 32 + (s >> 1) * 16 + (s & 1) * 8 + g;
        qsamp[s] = row / GROUP;
    }

    int ktStart = sp * TILES_PER_SPLIT;
    int ktEnd = ktStart + TILES_PER_SPLIT;
    if (ktEnd > 100) ktEnd = 100;

    for (int kt = ktStart; kt < ktEnd; kt++) {
        __syncthreads();
        int kBase = kt * 64;
        {
            const uint4* Kg = (const uint4*)(g_qcs + kBase * 64);
            const uint4* Vg = (const uint4*)(g_vcs + kBase * 64);
            for (int i = t; i < 1024; i += 128) {
                int key = i >> 4, j = i & 15;
                *(uint4*)(Ks + key * 64 + 4 * (j ^ (key & 7)))       = Kg[i];
                *(uint4*)(Vs + key * 64 + 4 * (j ^ (2 * (key & 3)))) = Vg[i];
            }
        }
        __syncthreads();

#pragma unroll
        for (int b = 0; b < 2; b++)
#pragma unroll
            for (int n = 0; n < 8; n++)
#pragma unroll
                for (int j = 0; j < 4; j++) S[b][n][j] = 0.f;

#pragma unroll
        for (int k0 = 0; k0 < 8; k0++) {
            int ch0 = 4 * ((2 * k0) ^ g);
            int ch1 = 4 * ((2 * k0 + 1) ^ g);
            uint32_t a[2][4];
#pragma unroll
            for (int b = 0; b < 2; b++) {
                int rL = (wm * 32 + b * 16 + g) * 64;
                a[b][0] = Qs[rL + ch0 + c4];
                a[b][1] = Qs[rL + 512 + ch0 + c4];
                a[b][2] = Qs[rL + ch1 + c4];
                a[b][3] = Qs[rL + 512 + ch1 + c4];
            }
#pragma unroll
            for (int n0 = 0; n0 < 8; n0++) {
                int key = n0 * 8 + g;
                uint32_t b0 = Ks[key * 64 + ch0 + c4];
                uint32_t b1 = Ks[key * 64 + ch1 + c4];
                mma_tf32(S[0][n0], a[0][0], a[0][1], a[0][2], a[0][3], b0, b1);
                mma_tf32(S[1][n0], a[1][0], a[1][1], a[1][2], a[1][3], b0, b1);
            }
        }

        float rm[4] = {-1e30f, -1e30f, -1e30f, -1e30f};
#pragma unroll
        for (int n0 = 0; n0 < 8; n0++) {
            int col0 = kBase + n0 * 8 + 2 * c4;
            int cs0 = col0 / GROUP, cs1 = (col0 + 1) / GROUP;
#pragma unroll
            for (int s = 0; s < 4; s++) {
                int b = s >> 1, h = s & 1;
                if (cs0 == qsamp[s]) S[b][n0][2 * h]     = -1e30f;
                if (cs1 == qsamp[s]) S[b][n0][2 * h + 1] = -1e30f;
                rm[s] = fmaxf(rm[s], fmaxf(S[b][n0][2 * h], S[b][n0][2 * h + 1]));
            }
        }
        float corr[4];
#pragma unroll
        for (int s = 0; s < 4; s++) {
            rm[s] = fmaxf(rm[s], __shfl_xor_sync(0xffffffffu, rm[s], 1));
            rm[s] = fmaxf(rm[s], __shfl_xor_sync(0xffffffffu, rm[s], 2));
            float mn = fmaxf(mv[s], rm[s]);
            corr[s] = __expf(mv[s] - mn);
            mv[s] = mn;
        }
        float ls[4] = {0.f, 0.f, 0.f, 0.f};
#pragma unroll
        for (int n0 = 0; n0 < 8; n0++) {
            int chp = 4 * ((2 * n0 + (c4 >> 1)) ^ g) + ((2 * c4) & 3);
#pragma unroll
            for (int s = 0; s < 4; s++) {
                int b = s >> 1, h = s & 1;
                float p0 = __expf(S[b][n0][2 * h]     - mv[s]);
                float p1 = __expf(S[b][n0][2 * h + 1] - mv[s]);
                ls[s] += p0 + p1;
                int row = wm * 32 + b * 16 + h * 8 + g;
                *(uint2*)(Ps + row * 64 + chp) = make_uint2(f2tf(p0), f2tf(p1));
            }
        }
#pragma unroll
        for (int s = 0; s < 4; s++) {
            ls[s] += __shfl_xor_sync(0xffffffffu, ls[s], 1);
            ls[s] += __shfl_xor_sync(0xffffffffu, ls[s], 2);
            lv[s] = lv[s] * corr[s] + ls[s];
            int b = s >> 1, h = s & 1;
#pragma unroll
            for (int n0 = 0; n0 < 8; n0++) {
                O[b][n0][2 * h]     *= corr[s];
                O[b][n0][2 * h + 1] *= corr[s];
            }
        }
        __syncwarp();

#pragma unroll
        for (int k0 = 0; k0 < 8; k0++) {
            int ch0 = 4 * ((2 * k0) ^ g);
            int ch1 = 4 * ((2 * k0 + 1) ^ g);
            uint32_t a[2][4];
#pragma unroll
            for (int b = 0; b < 2; b++) {
                int rL = (wm * 32 + b * 16 + g) * 64;
                a[b][0] = Ps[rL + ch0 + c4];
                a[b][1] = Ps[rL + 512 + ch0 + c4];
                a[b][2] = Ps[rL + ch1 + c4];
                a[b][3] = Ps[rL + 512 + ch1 + c4];
            }
            int ky0 = (k0 * 8 + c4) * 64;
            int ky1 = ky0 + 256;
            int sw = 2 * c4;
#pragma unroll
            for (int n0 = 0; n0 < 8; n0++) {
                int ch = 4 * ((2 * n0 + (g >> 2)) ^ sw) + (g & 3);
                uint32_t b0 = Vs[ky0 + ch];
                uint32_t b1 = Vs[ky1 + ch];
                mma_tf32(O[0][n0], a[0][0], a[0][1], a[0][2], a[0][3], b0, b1);
                mma_tf32(O[1][n0], a[1][0], a[1][1], a[1][2], a[1][3], b0, b1);
            }
        }
    }

    float* Op = g_Opart[sp];
#pragma unroll
    for (int b = 0; b < 2; b++) {
        int rowA = qBase + wm * 32 + b * 16 + g;
#pragma unroll
        for (int n0 = 0; n0 < 8; n0++) {
            int col = n0 * 8 + 2 * c4;
            *(float2*)(Op + rowA * 64 + col)       = make_float2(O[b][n0][0], O[b][n0][1]);
            *(float2*)(Op + (rowA + 8) * 64 + col) = make_float2(O[b][n0][2], O[b][n0][3]);
        }
    }
    if (c4 == 0) {
#pragma unroll
        for (int s = 0; s < 4; s++) {
            int row = qBase + wm * 32 + (s >> 1) * 16 + (s & 1) * 8 + g;
            g_mpart[sp][row] = mv[s];
            g_lpart[sp][row] = lv[s];
        }
    }
}

// ============================================================
// Kernel 3: combine split-K partials.
// ============================================================
__global__ __launch_bounds__(256) void cs_combine_kernel(float* __restrict__ outX)
{
    int gidx = blockIdx.x * 256 + threadIdx.x;
    int row = gidx >> 4;
    int e4 = gidx & 15;
    if (row >= N_ROWS) return;

    float m[NSPLIT];
    float M = -3.4e38f;
#pragma unroll
    for (int s = 0; s < NSPLIT; s++) { m[s] = g_mpart[s][row]; M = fmaxf(M, m[s]); }
    float wgt[NSPLIT];
    float denom = 0.f;
#pragma unroll
    for (int s = 0; s < NSPLIT; s++) {
        wgt[s] = __expf(m[s] - M);
        denom += wgt[s] * g_lpart[s][row];
    }
    float inv = 1.f / denom;

    float4 o = {0.f, 0.f, 0.f, 0.f};
#pragma unroll
    for (int s = 0; s < NSPLIT; s++) {
        float4 a = ((const float4*)g_Opart[s])[row * 16 + e4];
        o.x = fmaf(a.x, wgt[s], o.x);
        o.y = fmaf(a.y, wgt[s], o.y);
        o.z = fmaf(a.z, wgt[s], o.z);
        o.w = fmaf(a.w, wgt[s], o.w);
    }
    o.x *= inv; o.y *= inv; o.z *= inv; o.w *= inv;
    ((float4*)outX)[row * 16 + e4] = o;
}

// ============================================================
extern "C" void kernel_launch(void* const* d_in, const int* in_sizes, int n_in,
                              void* d_out, int out_size)
{
    const float* x    = (const float*)d_in[0];
    const float* cb   = (const float*)d_in[1];
    const float* Wqis = (const float*)d_in[2];  const float* bqis = (const float*)d_in[3];
    const float* Wkis = (const float*)d_in[4];  const float* bkis = (const float*)d_in[5];
    const float* Wvis = (const float*)d_in[6];  const float* bvis = (const float*)d_in[7];
    const float* Wqcs = (const float*)d_in[8];  const float* bqcs = (const float*)d_in[9];
    const float* Wkcs = (const float*)d_in[10]; const float* bkcs = (const float*)d_in[11];
    const float* Wvcs = (const float*)d_in[12]; const float* bvcs = (const float*)d_in[13];
    float* out = (float*)d_out;

    cudaFuncSetAttribute(proj_kernel,
                         cudaFuncAttributeMaxDynamicSharedMemorySize, 98816);
    cudaFuncSetAttribute(attn_kernel,
                         cudaFuncAttributeMaxDynamicSharedMemorySize, 98304);

    proj_kernel<<<300, 256, 98816>>>(x, Wqis, bqis, Wkis, bkis, Wvis, bvis,
                                     Wqcs, bqcs, Wkcs, bkcs, Wvcs, bvcs);
    attn_kernel<<<528, 128, 98304>>>(x, cb, out);
    cs_combine_kernel<<<(N_ROWS * 16 + 255) / 256, 256>>>(out + 2 * N_ROWS * DIMV);
}